// round 5
// baseline (speedup 1.0000x reference)
#include <cuda_runtime.h>
#include <cuda_bf16.h>

constexpr int TIMESTEPS = 1000;
constexpr int B = 4;
constexpr int N = 2048;                                // power of two
constexpr long long E = (long long)N * (N - 1) / 2;    // 2,096,128
constexpr int EI = (int)E;
constexpr int NBLK = B * (N / 2);                      // 4096 blocks
constexpr int NTHR = 256;

// Cross-block reduction scratch. g_count self-resets (atomicInc wrap) -> graph-replay safe.
__device__ float        g_partials[NBLK];
__device__ unsigned int g_count = 0;

struct Consts { float flip_t, omt, qt00, qt01, qt10, qt11; };

__device__ __forceinline__ float ex2(float x) {
    float r; asm("ex2.approx.f32 %0, %1;" : "=f"(r) : "f"(x)); return r;
}
__device__ __forceinline__ float rcp(float x) {
    float r; asm("rcp.approx.f32 %0, %1;" : "=f"(r) : "f"(x)); return r;
}

// Per-element loss term: qt via 4-entry LUT on (a!=0, x1); MUFU softplus.
__device__ __forceinline__ float term(int a, float uu, float x, const Consts& c) {
    bool  ab = (a != 0);
    float pa = ab ? c.omt : c.flip_t;          // Qt[t][a, 1]
    bool  x1 = uu < pa;                        // sampled bit
    float q0 = ab ? c.qt10 : c.qt00;
    float q1 = ab ? c.qt11 : c.qt01;
    float qt = x1 ? q1 : q0;
    float sp = __logf(1.0f + __expf(-fabsf(x)));   // log1p(exp(-|x|))
    return fmaf(-x, qt, fmaxf(x, 0.0f) + sp);
}

__device__ __forceinline__ float term4(int4 A, float4 U,
                                       float x0, float x1, float x2, float x3,
                                       const Consts& c) {
    return term(A.x, U.x, x0, c) + term(A.y, U.y, x1, c)
         + term(A.z, U.z, x2, c) + term(A.w, U.w, x3, c);
}

// One CTA per (b, k): rows i=k and i=N-1-k -> exactly 2047 elements.
// nv_A <= 255 (one vector slot/thread), nv_B in [256,511] (slot 1 always
// valid, slot 2 predicated) -> fully straight-line, loads front-batched.
__global__ __launch_bounds__(NTHR)
void loss_kernel(const int* __restrict__ adj, const int* __restrict__ t,
                 const float* __restrict__ u, const float* __restrict__ q,
                 float* __restrict__ out) {
    __shared__ float warp_sums[8];
    __shared__ bool  is_last;

    const int tid  = threadIdx.x;
    const int bidx = blockIdx.x;
    const int b    = bidx >> 10;        // / (N/2)
    const int k    = bidx & 1023;       // % (N/2)

    // Per-thread fp32 constants (MUFU) — no FP64, no barrier.
    Consts c;
    {
        const float L2_098 = -0.0291463173f;               // log2(0.98)
        int   tb = t[b];
        float pt = ex2((float)(tb + 1) * L2_098);          // 0.98^(t+1)
        int   tm1 = (tb + TIMESTEPS - 1) % TIMESTEPS;      // Qt[t-1] wraps at t=0
        float pp = ex2((float)(tm1 + 1) * L2_098);
        c.flip_t = 0.5f - 0.5f * pt;
        c.omt    = 0.5f + 0.5f * pt;
        float flip_p = 0.5f - 0.5f * pp;
        float omp    = 0.5f + 0.5f * pp;
        float r_omt  = rcp(c.omt);
        float r_flip = rcp(c.flip_t);
        // qt[ab][x1] = Qt0[x1,1] * Qt[t-1][ab,1] / Qt[t][ab,x1]
        c.qt00 = 0.01f * flip_p * r_omt;
        c.qt01 = 0.99f * flip_p * r_flip;
        c.qt10 = 0.01f * omp    * r_flip;
        c.qt11 = 0.99f * omp    * r_omt;
    }

    float s = 0.0f;

    // ---- half A: i = k, len = k in [0, 1023], nv <= 255 ----
    {
        const int i   = k;
        const int nv  = i >> 2;
        const int rem = i & 3;
        const int rowbase = ((b << 11) + i) << 11;           // (b*N+i)*N
        const int*   arow = adj + rowbase;
        const float* urow = u + rowbase;
        const float* qrow = q + b * EI + ((i * (i - 1)) >> 1);
        if (tid < nv) {
            int4   A = reinterpret_cast<const int4*>(arow)[tid];
            float4 U = reinterpret_cast<const float4*>(urow)[tid];
            const float* qp = qrow + (tid << 2);
            float x0 = qp[0], x1 = qp[1], x2 = qp[2], x3 = qp[3];
            s += term4(A, U, x0, x1, x2, x3, c);
        }
        if (tid < rem) {
            int j = (nv << 2) + tid;
            s += term(arow[j], urow[j], qrow[j], c);
        }
    }

    // ---- half B: i = N-1-k, len in [1024, 2047], nv in [256, 511] ----
    {
        const int i   = N - 1 - k;
        const int nv  = i >> 2;
        const int rem = i & 3;
        const int rowbase = ((b << 11) + i) << 11;
        const int*   arow = adj + rowbase;
        const float* urow = u + rowbase;
        const float* qrow = q + b * EI + ((i * (i - 1)) >> 1);

        // slot 1: unconditional (nv >= 256 > tid)
        int4   A1 = reinterpret_cast<const int4*>(arow)[tid];
        float4 U1 = reinterpret_cast<const float4*>(urow)[tid];
        const float* qp1 = qrow + (tid << 2);
        float a0 = qp1[0], a1 = qp1[1], a2 = qp1[2], a3 = qp1[3];

        // slot 2: predicated
        const int v2 = tid + NTHR;
        const bool p2 = v2 < nv;
        int4 A2 = make_int4(0, 0, 0, 0);
        float4 U2 = make_float4(1.f, 1.f, 1.f, 1.f);
        float b0 = 0.f, b1 = 0.f, b2 = 0.f, b3 = 0.f;
        if (p2) {
            A2 = reinterpret_cast<const int4*>(arow)[v2];
            U2 = reinterpret_cast<const float4*>(urow)[v2];
            const float* qp2 = qrow + (v2 << 2);
            b0 = qp2[0]; b1 = qp2[1]; b2 = qp2[2]; b3 = qp2[3];
        }

        s += term4(A1, U1, a0, a1, a2, a3, c);
        if (p2) s += term4(A2, U2, b0, b1, b2, b3, c);

        if (tid < rem) {
            int j = (nv << 2) + tid;
            s += term(arow[j], urow[j], qrow[j], c);
        }
    }

    // Block reduction
    #pragma unroll
    for (int off = 16; off; off >>= 1) s += __shfl_down_sync(0xffffffffu, s, off);
    const int lane = tid & 31, wid = tid >> 5;
    if (lane == 0) warp_sums[wid] = s;
    __syncthreads();
    if (wid == 0) {
        s = (lane < 8) ? warp_sums[lane] : 0.0f;
        #pragma unroll
        for (int off = 4; off; off >>= 1) s += __shfl_down_sync(0xffffffffu, s, off);
        if (lane == 0) g_partials[bidx] = s;
    }

    // Last-block-standing final reduction (counter wraps to 0 -> replayable)
    __threadfence();
    if (tid == 0) {
        unsigned v = atomicInc(&g_count, NBLK - 1);
        is_last = (v == NBLK - 1);
    }
    __syncthreads();
    if (is_last) {
        float acc = 0.0f;
        for (int idx = tid; idx < NBLK; idx += NTHR) acc += g_partials[idx];
        #pragma unroll
        for (int off = 16; off; off >>= 1) acc += __shfl_down_sync(0xffffffffu, acc, off);
        if (lane == 0) warp_sums[wid] = acc;
        __syncthreads();
        if (wid == 0) {
            acc = (lane < 8) ? warp_sums[lane] : 0.0f;
            #pragma unroll
            for (int off = 4; off; off >>= 1) acc += __shfl_down_sync(0xffffffffu, acc, off);
            if (lane == 0) out[0] = acc * (1.0f / (float)(B * E));
        }
    }
}

extern "C" void kernel_launch(void* const* d_in, const int* in_sizes, int n_in,
                              void* d_out, int out_size) {
    // metadata order: adj_start (int32), t (int32), u (f32), q_approx (f32)
    const int*   adj = (const int*)d_in[0];
    const int*   t   = (const int*)d_in[1];
    const float* u   = (const float*)d_in[2];
    const float* q   = (const float*)d_in[3];
    float* out = (float*)d_out;

    loss_kernel<<<NBLK, NTHR>>>(adj, t, u, q, out);
}